// round 16
// baseline (speedup 1.0000x reference)
#include <cuda_runtime.h>
#include <cuda_bf16.h>
#include <cstdint>

#define BB 8
#define CC 512
#define DQ 64
#define HH 128
#define WW 128
#define HWW 16384
#define GAMMA_ 1.0f

// dynamic smem double buffer: per buffer 4 tiles of 16*136 uint32 (2176 each)
#define TILE_U32 2176
#define BUF_U32  8704
#define DYN_SMEM_BYTES (2*BUF_U32*4)

// ---------------- scratch (device globals; no allocation) ----------------
__device__ float g_q [BB*DQ*HWW];        // [B,DQ,H,W]
__device__ float g_k [BB*DQ*HWW];        // [B,DQ,H,W]
__device__ float g_oH[BB*WW*CC*HH];      // [B,W,C,H]
__device__ float2 g_statH[BB*WW*HH];     // per (b,w,h): partial (max, sum) over H rows
__device__ float2 g_statW[BB*HH*WW];     // per (b,h,w): partial over W rows
__device__ float g_fH[BB*WW*HH];         // column factors for agg_H
__device__ float g_fW[BB*HH*WW];         // column factors for agg_W

// packed bf16 hi/lo (uint32 = two consecutive-K bf16, low half = even k)
__device__ uint32_t g_Wp_h[256*640];               // [kp][m]
__device__ uint32_t g_Wp_l[256*640];
__device__ uint32_t g_vWkm_h[(size_t)BB*HH*64*512]; // [b*HH+h][wp][c]
__device__ uint32_t g_vWkm_l[(size_t)BB*HH*64*512];
__device__ uint32_t g_vHkm_h[(size_t)BB*WW*64*512]; // [b*WW+w][hp][c]
__device__ uint32_t g_vHkm_l[(size_t)BB*WW*64*512];
__device__ uint32_t g_aHkm_h[(size_t)BB*WW*64*128]; // [b*WW+w][gp][h]  (unnormalized)
__device__ uint32_t g_aHkm_l[(size_t)BB*WW*64*128];
__device__ uint32_t g_aWkm_h[(size_t)BB*HH*64*128]; // [b*HH+h][vp][w]  (unnormalized)
__device__ uint32_t g_aWkm_l[(size_t)BB*HH*64*128];
__device__ uint32_t g_qWkm_h[(size_t)BB*HH*32*128]; // [b*HH+h][dp][w]
__device__ uint32_t g_qWkm_l[(size_t)BB*HH*32*128];
__device__ uint32_t g_kWkm_h[(size_t)BB*HH*32*128];
__device__ uint32_t g_kWkm_l[(size_t)BB*HH*32*128];
__device__ uint32_t g_qHkm_h[(size_t)BB*WW*32*128]; // [b*WW+w][dp][h]
__device__ uint32_t g_qHkm_l[(size_t)BB*WW*32*128];
__device__ uint32_t g_kHkm_h[(size_t)BB*WW*32*128];
__device__ uint32_t g_kHkm_l[(size_t)BB*WW*32*128];

// ---------------- helpers ----------------
__device__ __forceinline__ void split_pack(float v0, float v1, uint32_t& hi, uint32_t& lo){
    __nv_bfloat16 h0 = __float2bfloat16(v0);
    __nv_bfloat16 h1 = __float2bfloat16(v1);
    __nv_bfloat16 l0 = __float2bfloat16(v0 - __bfloat162float(h0));
    __nv_bfloat16 l1 = __float2bfloat16(v1 - __bfloat162float(h1));
    hi = ((uint32_t)__bfloat16_as_ushort(h1) << 16) | (uint32_t)__bfloat16_as_ushort(h0);
    lo = ((uint32_t)__bfloat16_as_ushort(l1) << 16) | (uint32_t)__bfloat16_as_ushort(l0);
}
__device__ __forceinline__ void mma_bf16(float* c, const uint32_t* a, const uint32_t* b){
    asm volatile("mma.sync.aligned.m16n8k16.row.col.f32.bf16.bf16.f32 "
        "{%0,%1,%2,%3}, {%4,%5,%6,%7}, {%8,%9}, {%0,%1,%2,%3};"
        : "+f"(c[0]), "+f"(c[1]), "+f"(c[2]), "+f"(c[3])
        : "r"(a[0]), "r"(a[1]), "r"(a[2]), "r"(a[3]), "r"(b[0]), "r"(b[1]));
}

// ---------------- pack W (tiny) ----------------
__global__ void __launch_bounds__(256) pack_W_kernel(const float* __restrict__ Wq,
                                                     const float* __restrict__ Wk,
                                                     const float* __restrict__ Wv)
{
    int u = blockIdx.x * 256 + threadIdx.x;
    if (u >= 256*160) return;
    int kp = u / 160;
    int m4 = u - kp*160;
    int m = m4*4;
    int c0 = 2*kp, c1 = 2*kp+1;
    float v0[4], v1[4];
    #pragma unroll
    for (int j = 0; j < 4; j++) {
        int mm = m + j;
        if (mm < 64)       { v0[j] = Wq[(size_t)c0*DQ + mm];       v1[j] = Wq[(size_t)c1*DQ + mm]; }
        else if (mm < 128) { v0[j] = Wk[(size_t)c0*DQ + mm-64];    v1[j] = Wk[(size_t)c1*DQ + mm-64]; }
        else               { v0[j] = Wv[(size_t)c0*CC + mm-128];   v1[j] = Wv[(size_t)c1*CC + mm-128]; }
    }
    uint4 hi, lo;
    split_pack(v0[0], v1[0], hi.x, lo.x);
    split_pack(v0[1], v1[1], hi.y, lo.y);
    split_pack(v0[2], v1[2], hi.z, lo.z);
    split_pack(v0[3], v1[3], hi.w, lo.w);
    *(uint4*)(g_Wp_h + (size_t)kp*640 + m) = hi;
    *(uint4*)(g_Wp_l + (size_t)kp*640 + m) = lo;
}

// ---------------- HMMA projection GEMM (double-buffered, split N-tile) --------
// N-tile = pixels {h=2j, 2j+1} x {w in [whalf*64, whalf*64+64)}; col n -> pixel
// offset pix(n) = ((n&64)<<1) + (n&63) relative to base (2j*128 + whalf*64).
extern __shared__ uint32_t dynS[];

__device__ __forceinline__ void proj_load_tile(int it, uint32_t* buf, int tid,
                                               int mTile, const float* __restrict__ xB)
{
    const int kp0 = it * 16;
    uint32_t* Ah = buf;
    uint32_t* Al = buf + TILE_U32;
    uint32_t* Bh = buf + 2*TILE_U32;
    uint32_t* Bl = buf + 3*TILE_U32;
    #pragma unroll
    for (int i = 0; i < 2; i++) {
        int f = tid + i*256;
        int kp = f >> 5, c4 = (f & 31) * 4;
        int pix = ((c4 & 64) << 1) + (c4 & 63);
        *(uint4*)&Ah[kp*136 + c4] = *(const uint4*)&g_Wp_h[(size_t)(kp0+kp)*640 + mTile + c4];
        *(uint4*)&Al[kp*136 + c4] = *(const uint4*)&g_Wp_l[(size_t)(kp0+kp)*640 + mTile + c4];
        const float* p0 = xB + (size_t)(2*(kp0+kp))*HWW + pix;
        float4 r0 = *(const float4*)p0;
        float4 r1 = *(const float4*)(p0 + HWW);
        uint4 bh4, bl4;
        split_pack(r0.x, r1.x, bh4.x, bl4.x);
        split_pack(r0.y, r1.y, bh4.y, bl4.y);
        split_pack(r0.z, r1.z, bh4.z, bl4.z);
        split_pack(r0.w, r1.w, bh4.w, bl4.w);
        *(uint4*)&Bh[kp*136 + c4] = bh4;
        *(uint4*)&Bl[kp*136 + c4] = bl4;
    }
}

__global__ void __launch_bounds__(256, 2) mma_proj_kernel(
    const float* __restrict__ x,
    const float* __restrict__ bq, const float* __restrict__ bk, const float* __restrict__ bvv)
{
    const int tid = threadIdx.x;
    const int wid = tid >> 5, lane = tid & 31;
    const int gid = lane >> 2, tig = lane & 3;
    const int wm0 = (wid >> 2) * 64;
    const int wn0 = (wid & 3) * 32;
    const int mTile = blockIdx.x * 128;
    const int jIdx = blockIdx.y >> 1;          // h-pair index
    const int whalf = blockIdx.y & 1;          // w half
    const int yBase = jIdx*256 + whalf*64;     // base pixel = 2j*128 + whalf*64
    const int b = blockIdx.z;

    float acc[4][4][4];
    #pragma unroll
    for (int i = 0; i < 4; i++)
        #pragma unroll
        for (int j = 0; j < 4; j++)
            #pragma unroll
            for (int r = 0; r < 4; r++) acc[i][j][r] = 0.f;

    const float* xB = x + (size_t)b*CC*HWW + yBase;

    proj_load_tile(0, dynS, tid, mTile, xB);
    __syncthreads();

    for (int it = 0; it < 16; ++it) {
        if (it < 15)
            proj_load_tile(it+1, dynS + ((it+1)&1)*BUF_U32, tid, mTile, xB);
        const uint32_t* Ah = dynS + (it&1)*BUF_U32;
        const uint32_t* Al = Ah + TILE_U32;
        const uint32_t* Bh = Ah + 2*TILE_U32;
        const uint32_t* Bl = Ah + 3*TILE_U32;
        #pragma unroll
        for (int ks = 0; ks < 2; ks++) {
            const int kb = ks * 8;
            uint32_t ah[4][4], al[4][4], bh[4][2], bl[4][2];
            #pragma unroll
            for (int mi = 0; mi < 4; mi++) {
                int m = wm0 + mi*16 + gid;
                ah[mi][0] = Ah[(kb+tig  )*136 + m];
                ah[mi][1] = Ah[(kb+tig  )*136 + m+8];
                ah[mi][2] = Ah[(kb+tig+4)*136 + m];
                ah[mi][3] = Ah[(kb+tig+4)*136 + m+8];
                al[mi][0] = Al[(kb+tig  )*136 + m];
                al[mi][1] = Al[(kb+tig  )*136 + m+8];
                al[mi][2] = Al[(kb+tig+4)*136 + m];
                al[mi][3] = Al[(kb+tig+4)*136 + m+8];
            }
            #pragma unroll
            for (int nj = 0; nj < 4; nj++) {
                int n = wn0 + nj*8 + gid;
                bh[nj][0] = Bh[(kb+tig  )*136 + n];
                bh[nj][1] = Bh[(kb+tig+4)*136 + n];
                bl[nj][0] = Bl[(kb+tig  )*136 + n];
                bl[nj][1] = Bl[(kb+tig+4)*136 + n];
            }
            #pragma unroll
            for (int mi = 0; mi < 4; mi++)
                #pragma unroll
                for (int nj = 0; nj < 4; nj++) {
                    mma_bf16(acc[mi][nj], ah[mi], bh[nj]);
                    mma_bf16(acc[mi][nj], ah[mi], bl[nj]);
                    mma_bf16(acc[mi][nj], al[mi], bh[nj]);
                }
        }
        __syncthreads();
    }

    if (mTile == 0) {
        // q/k rows -> fp32, pixel-remapped columns
        #pragma unroll
        for (int mi = 0; mi < 4; mi++) {
            #pragma unroll
            for (int half = 0; half < 2; half++) {
                int row = wm0 + mi*16 + gid + half*8;
                float bias; float* optr;
                if (row < 64) { bias = bq[row];    optr = g_q + ((size_t)b*DQ + row)     *HWW; }
                else          { bias = bk[row-64]; optr = g_k + ((size_t)b*DQ + (row-64))*HWW; }
                #pragma unroll
                for (int nj = 0; nj < 4; nj++) {
                    int n = wn0 + nj*8 + 2*tig;
                    int pix = ((n & 64) << 1) + (n & 63);
                    float2 f2;
                    f2.x = acc[mi][nj][half*2+0] + bias;
                    f2.y = acc[mi][nj][half*2+1] + bias;
                    *(float2*)(optr + yBase + pix) = f2;
                }
            }
        }
    } else {
        // v rows: stage fp32 tile to smem [n][c] (pitch 132), then pack both layouts
        float* smf = (float*)dynS;
        #pragma unroll
        for (int mi = 0; mi < 4; mi++) {
            #pragma unroll
            for (int half = 0; half < 2; half++) {
                int rowL = wm0 + mi*16 + gid + half*8;
                float bias = bvv[mTile - 128 + rowL];
                #pragma unroll
                for (int nj = 0; nj < 4; nj++) {
                    int col = wn0 + nj*8 + 2*tig;
                    smf[(col  )*132 + rowL] = acc[mi][nj][half*2+0] + bias;
                    smf[(col+1)*132 + rowL] = acc[mi][nj][half*2+1] + bias;
                }
            }
        }
        __syncthreads();
        const int cBase = mTile - 128;
        // vWkm: w-pairs.  n = hOff*64 + 2*wli (+1)
        #pragma unroll 4
        for (int itw = 0; itw < 32; itw++) {
            int u = tid + itw*256;
            int c = u & 127;
            int pr = u >> 7;                 // 0..63
            int hOff = pr >> 5, wli = pr & 31;
            int n = hOff*64 + 2*wli;
            uint32_t hh, ll;
            split_pack(smf[n*132 + c], smf[(n+1)*132 + c], hh, ll);
            size_t o = ((size_t)(b*HH + 2*jIdx + hOff)*64 + whalf*32 + wli)*512 + cBase + c;
            g_vWkm_h[o] = hh; g_vWkm_l[o] = ll;
        }
        // vHkm: h-pairs. values at n=wl (h=2j) and n=wl+64 (h=2j+1)
        #pragma unroll 4
        for (int ith = 0; ith < 32; ith++) {
            int u = tid + ith*256;
            int c = u & 127;
            int wl = u >> 7;                 // 0..63
            uint32_t hh, ll;
            split_pack(smf[wl*132 + c], smf[(wl+64)*132 + c], hh, ll);
            size_t o = ((size_t)(b*WW + whalf*64 + wl)*64 + jIdx)*512 + cBase + c;
            g_vHkm_h[o] = hh; g_vHkm_l[o] = ll;
        }
    }
}

// ---------------- packA/packB: q/k energy operands (validated R7) ----------------
__device__ __forceinline__ void packA_body(const float* __restrict__ src,
                                           uint32_t* __restrict__ dh,
                                           uint32_t* __restrict__ dl)
{
    __shared__ float t[32][33];
    int s = blockIdx.z;
    int b = s >> 7, h = s & 127;
    int w0 = blockIdx.x*32, d0 = blockIdx.y*32;
    int tx = threadIdx.x, ty = threadIdx.y;
    const float* S = src + (size_t)b*DQ*HWW + (size_t)h*WW;
    #pragma unroll
    for (int j = 0; j < 32; j += 8)
        t[ty+j][tx] = S[(size_t)(d0+ty+j)*HWW + w0 + tx];
    __syncthreads();
    #pragma unroll
    for (int j = 0; j < 16; j += 8) {
        int kp = ty + j;
        uint32_t hi, lo;
        split_pack(t[2*kp][tx], t[2*kp+1][tx], hi, lo);
        size_t o = ((size_t)s*32 + (d0>>1) + kp)*128 + w0 + tx;
        dh[o] = hi; dl[o] = lo;
    }
}
__global__ void packA_q_kernel(){ packA_body(g_q, g_qWkm_h, g_qWkm_l); }
__global__ void packA_k_kernel(){ packA_body(g_k, g_kWkm_h, g_kWkm_l); }

__device__ __forceinline__ void packB_body(const float* __restrict__ src,
                                           uint32_t* __restrict__ dh,
                                           uint32_t* __restrict__ dl)
{
    __shared__ float t[8][32][33];
    int z = blockIdx.z;
    int b = z >> 3, d0 = (z & 7) * 8;
    int w0 = blockIdx.x*32, h0 = blockIdx.y*32;
    int tid = threadIdx.x;
    int tx = tid & 31, ty = tid >> 5;
    #pragma unroll
    for (int dd = 0; dd < 8; dd++)
        #pragma unroll
        for (int j = 0; j < 32; j += 8)
            t[dd][ty+j][tx] = src[((size_t)b*DQ + d0+dd)*HWW + (size_t)(h0+ty+j)*WW + w0 + tx];
    __syncthreads();
    #pragma unroll
    for (int it = 0; it < 16; it++) {
        int idx = tid + it*256;
        int hl = idx & 31, wl = (idx >> 5) & 31, dpl = idx >> 10;
        uint32_t hi, lo;
        split_pack(t[2*dpl][hl][wl], t[2*dpl+1][hl][wl], hi, lo);
        size_t o = (((size_t)b*WW + w0 + wl)*32 + (d0>>1) + dpl)*128 + h0 + hl;
        dh[o] = hi; dl[o] = lo;
    }
}
__global__ void __launch_bounds__(256) packB_q_kernel(){ packB_body(g_q, g_qHkm_h, g_qHkm_l); }
__global__ void __launch_bounds__(256) packB_k_kernel(){ packB_body(g_k, g_kHkm_h, g_kHkm_l); }

// ---------------- energy: HMMA -> unnormalized packed att + stat partials (R9) ----
template<int MASK>
__device__ __forceinline__ void energy_mma_body(
    const uint32_t* __restrict__ Qh, const uint32_t* __restrict__ Ql,
    const uint32_t* __restrict__ Kh, const uint32_t* __restrict__ Kl,
    uint32_t* __restrict__ dh, uint32_t* __restrict__ dl,
    float2* __restrict__ statOut)
{
    __shared__ uint32_t sAh[16][136], sAl[16][136], sBh[16][136], sBl[16][136];
    __shared__ float red[128][17];
    __shared__ float rmax[128];

    const int tid = threadIdx.x;
    const int wid = tid >> 5, lane = tid & 31;
    const int gid = lane >> 2, tig = lane & 3;
    const int wm0 = (wid >> 2) * 64;
    const int wn0 = (wid & 3) * 32;
    const int cg  = (wid & 3) * 4 + tig;
    const int s = blockIdx.z;

    const uint32_t* Qh_s = Qh + (size_t)s*32*128;
    const uint32_t* Ql_s = Ql + (size_t)s*32*128;
    const uint32_t* Kh_s = Kh + (size_t)s*32*128;
    const uint32_t* Kl_s = Kl + (size_t)s*32*128;

    float acc[4][4][4];
    #pragma unroll
    for (int i = 0; i < 4; i++)
        #pragma unroll
        for (int j = 0; j < 4; j++)
            #pragma unroll
            for (int r = 0; r < 4; r++) acc[i][j][r] = 0.f;

    for (int ch = 0; ch < 2; ++ch) {
        const int kp0 = ch * 16;
        #pragma unroll
        for (int i = 0; i < 2; i++) {
            int f = tid + i*256;
            int kp = f >> 5, c4 = (f & 31) * 4;
            *(uint4*)&sAh[kp][c4] = *(const uint4*)(Qh_s + (size_t)(kp0+kp)*128 + c4);
            *(uint4*)&sAl[kp][c4] = *(const uint4*)(Ql_s + (size_t)(kp0+kp)*128 + c4);
            *(uint4*)&sBh[kp][c4] = *(const uint4*)(Kh_s + (size_t)(kp0+kp)*128 + c4);
            *(uint4*)&sBl[kp][c4] = *(const uint4*)(Kl_s + (size_t)(kp0+kp)*128 + c4);
        }
        __syncthreads();
        #pragma unroll
        for (int ks = 0; ks < 2; ks++) {
            const int kb = ks * 8;
            uint32_t ah[4][4], al[4][4], bh[4][2], bl[4][2];
            #pragma unroll
            for (int mi = 0; mi < 4; mi++) {
                int m = wm0 + mi*16 + gid;
                ah[mi][0] = sAh[kb+tig  ][m];
                ah[mi][1] = sAh[kb+tig  ][m+8];
                ah[mi][2] = sAh[kb+tig+4][m];
                ah[mi][3] = sAh[kb+tig+4][m+8];
                al[mi][0] = sAl[kb+tig  ][m];
                al[mi][1] = sAl[kb+tig  ][m+8];
                al[mi][2] = sAl[kb+tig+4][m];
                al[mi][3] = sAl[kb+tig+4][m+8];
            }
            #pragma unroll
            for (int nj = 0; nj < 4; nj++) {
                int n = wn0 + nj*8 + gid;
                bh[nj][0] = sBh[kb+tig  ][n];
                bh[nj][1] = sBh[kb+tig+4][n];
                bl[nj][0] = sBl[kb+tig  ][n];
                bl[nj][1] = sBl[kb+tig+4][n];
            }
            #pragma unroll
            for (int mi = 0; mi < 4; mi++)
                #pragma unroll
                for (int nj = 0; nj < 4; nj++) {
                    mma_bf16(acc[mi][nj], ah[mi], bh[nj]);
                    mma_bf16(acc[mi][nj], ah[mi], bl[nj]);
                    mma_bf16(acc[mi][nj], al[mi], bh[nj]);
                }
        }
        __syncthreads();
    }

    const float NINF = __int_as_float(0xff800000);
    if (MASK) {
        #pragma unroll
        for (int mi = 0; mi < 4; mi++)
            #pragma unroll
            for (int half = 0; half < 2; half++) {
                int row = wm0 + mi*16 + gid + half*8;
                #pragma unroll
                for (int nj = 0; nj < 4; nj++) {
                    int col = wn0 + nj*8 + 2*tig;
                    if (row == col)   acc[mi][nj][half*2+0] = NINF;
                    if (row == col+1) acc[mi][nj][half*2+1] = NINF;
                }
            }
    }

    #pragma unroll
    for (int mi = 0; mi < 4; mi++)
        #pragma unroll
        for (int half = 0; half < 2; half++) {
            int row = wm0 + mi*16 + gid + half*8;
            float m8 = NINF;
            #pragma unroll
            for (int nj = 0; nj < 4; nj++) {
                m8 = fmaxf(m8, acc[mi][nj][half*2+0]);
                m8 = fmaxf(m8, acc[mi][nj][half*2+1]);
            }
            red[row][cg] = m8;
        }
    __syncthreads();
    if (tid < 128) {
        float m = red[tid][0];
        #pragma unroll
        for (int j = 1; j < 16; j++) m = fmaxf(m, red[tid][j]);
        rmax[tid] = m;
    }
    __syncthreads();

    #pragma unroll
    for (int mi = 0; mi < 4; mi++)
        #pragma unroll
        for (int half = 0; half < 2; half++) {
            int row = wm0 + mi*16 + gid + half*8;
            float rm = rmax[row];
            float s8 = 0.f;
            #pragma unroll
            for (int nj = 0; nj < 4; nj++) {
                int col = wn0 + nj*8 + 2*tig;
                float e0 = __expf(acc[mi][nj][half*2+0] - rm);
                float e1 = __expf(acc[mi][nj][half*2+1] - rm);
                s8 += e0 + e1;
                uint32_t hi, lo;
                split_pack(e0, e1, hi, lo);
                size_t o = (size_t)s*8192 + (size_t)(col>>1)*128 + row;
                dh[o] = hi; dl[o] = lo;
            }
            red[row][cg] = s8;
        }
    __syncthreads();
    if (tid < 128) {
        float ssum = red[tid][0];
        #pragma unroll
        for (int j = 1; j < 16; j++) ssum += red[tid][j];
        statOut[(size_t)s*128 + tid] = make_float2(rmax[tid], ssum);
    }
}
__global__ void __launch_bounds__(256) energy_H_mma_kernel(){
    energy_mma_body<1>(g_qHkm_h, g_qHkm_l, g_kHkm_h, g_kHkm_l,
                       g_aHkm_h, g_aHkm_l, g_statH);
}
__global__ void __launch_bounds__(256) energy_W_mma_kernel(){
    energy_mma_body<0>(g_qWkm_h, g_qWkm_l, g_kWkm_h, g_kWkm_l,
                       g_aWkm_h, g_aWkm_l, g_statW);
}

// ---------------- merge stats -> per-orientation column factors (R9) --------------
__global__ void __launch_bounds__(256) combine_stat_kernel()
{
    int u = blockIdx.x*256 + threadIdx.x;   // b*HWW + h*WW + w
    int b = u >> 14;
    int hw = u & 16383;
    int h = hw >> 7, w = hw & 127;
    size_t iH = (size_t)(b*WW + w)*128 + h;
    size_t iW = (size_t)(b*HH + h)*128 + w;
    float2 sh = g_statH[iH];
    float2 sw = g_statW[iW];
    float m = fmaxf(sh.x, sw.x);
    float eh = __expf(sh.x - m), ew = __expf(sw.x - m);
    float invZ = 1.0f / (sh.y*eh + sw.y*ew);
    g_fH[iH] = eh * invZ;
    g_fW[iW] = ew * invZ;
}

// ---------------- HMMA aggregation (R13-validated, double-buffered) -----------
__device__ __forceinline__ void agg_load_tile(int ch, uint32_t* buf, int tid,
    const uint32_t* __restrict__ Vh_s, const uint32_t* __restrict__ Vl_s,
    const uint32_t* __restrict__ Ah_s, const uint32_t* __restrict__ Al_s)
{
    const int kp0 = ch * 16;
    uint32_t* Ah = buf;
    uint32_t* Al = buf + TILE_U32;
    uint32_t* Bh = buf + 2*TILE_U32;
    uint32_t* Bl = buf + 3*TILE_U32;
    #pragma unroll
    for (int i = 0; i < 2; i++) {
        int f = tid + i*256;
        int kp = f >> 5, c4 = (f & 31) * 4;
        *(uint4*)&Ah[kp*136 + c4] = *(const uint4*)(Vh_s + (size_t)(kp0+kp)*512 + c4);
        *(uint4*)&Al[kp*136 + c4] = *(const uint4*)(Vl_s + (size_t)(kp0+kp)*512 + c4);
        *(uint4*)&Bh[kp*136 + c4] = *(const uint4*)(Ah_s + (size_t)(kp0+kp)*128 + c4);
        *(uint4*)&Bl[kp*136 + c4] = *(const uint4*)(Al_s + (size_t)(kp0+kp)*128 + c4);
    }
}

__device__ __forceinline__ void agg_mma_body(
    const uint32_t* __restrict__ Vh, const uint32_t* __restrict__ Vl,
    const uint32_t* __restrict__ Ah_g, const uint32_t* __restrict__ Al_g,
    const float* __restrict__ fac,
    float* __restrict__ O, long oB, long oS, long oRow,
    const float* __restrict__ xAdd)
{
    __shared__ float sFac[128];

    const int tid = threadIdx.x;
    const int wid = tid >> 5, lane = tid & 31;
    const int gid = lane >> 2, tig = lane & 3;
    const int wm0 = (wid >> 2) * 64;
    const int wn0 = (wid & 3) * 32;
    const int mTile = blockIdx.x * 128;
    const int s = blockIdx.z;
    const int b = s >> 7, ss = s & 127;

    const uint32_t* Vh_s = Vh + (size_t)s*64*512 + mTile;
    const uint32_t* Vl_s = Vl + (size_t)s*64*512 + mTile;
    const uint32_t* Ah_s = Ah_g + (size_t)s*64*128;
    const uint32_t* Al_s = Al_g + (size_t)s*64*128;
    const size_t oBase = (size_t)b*oB + (size_t)ss*oS + (size_t)mTile*oRow;
    float* O_s = O + oBase;
    const float* X_s = xAdd ? (xAdd + oBase) : nullptr;

    if (tid < 128) sFac[tid] = fac[(size_t)s*128 + tid];

    float acc[4][4][4];
    #pragma unroll
    for (int i = 0; i < 4; i++)
        #pragma unroll
        for (int j = 0; j < 4; j++)
            #pragma unroll
            for (int r = 0; r < 4; r++) acc[i][j][r] = 0.f;

    agg_load_tile(0, dynS, tid, Vh_s, Vl_s, Ah_s, Al_s);
    __syncthreads();

    for (int ch = 0; ch < 4; ++ch) {
        if (ch < 3)
            agg_load_tile(ch+1, dynS + ((ch+1)&1)*BUF_U32, tid, Vh_s, Vl_s, Ah_s, Al_s);
        const uint32_t* Ah = dynS + (ch&1)*BUF_U32;
        const uint32_t* Al = Ah + TILE_U32;
        const uint32_t* Bh = Ah + 2*TILE_U32;
        const uint32_t* Bl = Ah + 3*TILE_U32;
        #pragma unroll
        for (int ks = 0; ks < 2; ks++) {
            const int kb = ks * 8;
            uint32_t ah[4][4], al[4][4], bh[4][2], bl[4][2];
            #pragma unroll
            for (int mi = 0; mi < 4; mi++) {
                int m = wm0 + mi*16 + gid;
                ah[mi][0] = Ah[(kb+tig  )*136 + m];
                ah[mi][1] = Ah[(kb+tig  )*136 + m+8];
                ah[mi][2] = Ah[(kb+tig+4)*136 + m];
                ah[mi][3] = Ah[(kb+tig+4)*136 + m+8];
                al[mi][0] = Al[(kb+tig  )*136 + m];
                al[mi][1] = Al[(kb+tig  )*136 + m+8];
                al[mi][2] = Al[(kb+tig+4)*136 + m];
                al[mi][3] = Al[(kb+tig+4)*136 + m+8];
            }
            #pragma unroll
            for (int nj = 0; nj < 4; nj++) {
                int n = wn0 + nj*8 + gid;
                bh[nj][0] = Bh[(kb+tig  )*136 + n];
                bh[nj][1] = Bh[(kb+tig+4)*136 + n];
                bl[nj][0] = Bl[(kb+tig  )*136 + n];
                bl[nj][1] = Bl[(kb+tig+4)*136 + n];
            }
            #pragma unroll
            for (int mi = 0; mi < 4; mi++)
                #pragma unroll
                for (int nj = 0; nj < 4; nj++) {
                    mma_bf16(acc[mi][nj], ah[mi], bh[nj]);
                    mma_bf16(acc[mi][nj], ah[mi], bl[nj]);
                    mma_bf16(acc[mi][nj], al[mi], bh[nj]);
                }
        }
        __syncthreads();
    }

    #pragma unroll
    for (int mi = 0; mi < 4; mi++) {
        #pragma unroll
        for (int half = 0; half < 2; half++) {
            int rowL = wm0 + mi*16 + gid + half*8;
            size_t roff = (size_t)rowL*oRow;
            #pragma unroll
            for (int nj = 0; nj < 4; nj++) {
                int col = wn0 + nj*8 + 2*tig;
                float2 f2;
                f2.x = acc[mi][nj][half*2+0] * sFac[col];
                f2.y = acc[mi][nj][half*2+1] * sFac[col+1];
                if (X_s) {
                    float2 xv = *(const float2*)(X_s + roff + col);
                    f2.x += xv.x; f2.y += xv.y;
                }
                *(float2*)(O_s + roff + col) = f2;
            }
        }
    }
}
__global__ void __launch_bounds__(256, 2) agg_H_mma_kernel(){
    agg_mma_body(g_vHkm_h, g_vHkm_l, g_aHkm_h, g_aHkm_l, g_fH, g_oH,
                 (long)WW*CC*HH, (long)CC*HH, (long)HH, nullptr);
}
__global__ void __launch_bounds__(256, 2) agg_W_mma_kernel(float* __restrict__ out,
                                                           const float* __restrict__ x){
    agg_mma_body(g_vWkm_h, g_vWkm_l, g_aWkm_h, g_aWkm_l, g_fW, out,
                 (long)CC*HWW, (long)WW, (long)HWW, x);
}

// ---------------- combine: out += GAMMA*out_H^T  (out already = out_W + x) ----------
__global__ void combine_kernel(float* __restrict__ out)
{
    __shared__ float t[32][33];
    int bc = blockIdx.z;
    int b = bc >> 9, c = bc & 511;
    int w0 = blockIdx.x*32, h0 = blockIdx.y*32;
    int tx = threadIdx.x, ty = threadIdx.y;
    #pragma unroll
    for (int k = 0; k < 32; k += 8) {
        int w = w0 + ty + k;
        int h = h0 + tx;
        t[ty+k][tx] = g_oH[(((size_t)b*WW + w)*CC + c)*HH + h];
    }
    __syncthreads();
    #pragma unroll
    for (int k = 0; k < 32; k += 8) {
        int h = h0 + ty + k;
        int w = w0 + tx;
        size_t idx = ((size_t)bc*HH + h)*WW + w;
        out[idx] = GAMMA_*t[tx][ty+k] + out[idx];
    }
}

// ---------------- launch ----------------
extern "C" void kernel_launch(void* const* d_in, const int* in_sizes, int n_in,
                              void* d_out, int out_size)
{
    const float* x  = (const float*)d_in[0];
    const float* Wq = (const float*)d_in[1];
    const float* bq = (const float*)d_in[2];
    const float* Wk = (const float*)d_in[3];
    const float* bk = (const float*)d_in[4];
    const float* Wv = (const float*)d_in[5];
    const float* bv = (const float*)d_in[6];
    float* out = (float*)d_out;

    cudaFuncSetAttribute(mma_proj_kernel,  cudaFuncAttributeMaxDynamicSharedMemorySize, DYN_SMEM_BYTES);
    cudaFuncSetAttribute(agg_H_mma_kernel, cudaFuncAttributeMaxDynamicSharedMemorySize, DYN_SMEM_BYTES);
    cudaFuncSetAttribute(agg_W_mma_kernel, cudaFuncAttributeMaxDynamicSharedMemorySize, DYN_SMEM_BYTES);

    dim3 tb(32, 8);

    pack_W_kernel<<<160, 256>>>(Wq, Wk, Wv);

    mma_proj_kernel<<<dim3(5, HWW/128, BB), 256, DYN_SMEM_BYTES>>>(x, bq, bk, bv);

    packA_q_kernel<<<dim3(4, 2, BB*HH), tb>>>();
    packA_k_kernel<<<dim3(4, 2, BB*HH), tb>>>();
    packB_q_kernel<<<dim3(4, 4, BB*8), 256>>>();
    packB_k_kernel<<<dim3(4, 4, BB*8), 256>>>();

    energy_H_mma_kernel<<<dim3(1, 1, BB*WW), 256>>>();
    energy_W_mma_kernel<<<dim3(1, 1, BB*HH), 256>>>();

    combine_stat_kernel<<<(BB*HWW)/256, 256>>>();

    agg_H_mma_kernel<<<dim3(4, 1, BB*WW), 256, DYN_SMEM_BYTES>>>();
    agg_W_mma_kernel<<<dim3(4, 1, BB*HH), 256, DYN_SMEM_BYTES>>>(out, x);

    combine_kernel<<<dim3(WW/32, HH/32, BB*CC), tb>>>(out);
}

// round 17
// speedup vs baseline: 1.4572x; 1.4572x over previous
#include <cuda_runtime.h>
#include <cuda_bf16.h>
#include <cstdint>

#define BB 8
#define CC 512
#define DQ 64
#define HH 128
#define WW 128
#define HWW 16384
#define GAMMA_ 1.0f

// dynamic smem double buffer: per buffer 4 tiles of 16*136 uint32 (2176 each)
#define TILE_U32 2176
#define BUF_U32  8704
#define DYN_SMEM_BYTES (2*BUF_U32*4)

// ---------------- scratch (device globals; no allocation) ----------------
__device__ float g_q [BB*DQ*HWW];        // [B,DQ,H,W]
__device__ float g_k [BB*DQ*HWW];        // [B,DQ,H,W]
__device__ float g_oH[BB*WW*CC*HH];      // [B,W,C,H]
__device__ float2 g_statH[BB*WW*HH];     // per (b,w,h): partial (max, sum) over H rows
__device__ float2 g_statW[BB*HH*WW];     // per (b,h,w): partial over W rows
__device__ float g_fH[BB*WW*HH];         // column factors for agg_H
__device__ float g_fW[BB*HH*WW];         // column factors for agg_W

// packed bf16 hi/lo (uint32 = two consecutive-K bf16, low half = even k)
__device__ uint32_t g_Wp_h[256*640];               // [kp][m]
__device__ uint32_t g_Wp_l[256*640];
__device__ uint32_t g_vWkm_h[(size_t)BB*HH*64*512]; // [b*HH+h][wp][c]
__device__ uint32_t g_vWkm_l[(size_t)BB*HH*64*512];
__device__ uint32_t g_vHkm_h[(size_t)BB*WW*64*512]; // [b*WW+w][hp][c]
__device__ uint32_t g_vHkm_l[(size_t)BB*WW*64*512];
__device__ uint32_t g_aHkm_h[(size_t)BB*WW*64*128]; // [b*WW+w][gp][h]  (unnormalized)
__device__ uint32_t g_aHkm_l[(size_t)BB*WW*64*128];
__device__ uint32_t g_aWkm_h[(size_t)BB*HH*64*128]; // [b*HH+h][vp][w]  (unnormalized)
__device__ uint32_t g_aWkm_l[(size_t)BB*HH*64*128];
__device__ uint32_t g_qWkm_h[(size_t)BB*HH*32*128]; // [b*HH+h][dp][w]
__device__ uint32_t g_qWkm_l[(size_t)BB*HH*32*128];
__device__ uint32_t g_kWkm_h[(size_t)BB*HH*32*128];
__device__ uint32_t g_kWkm_l[(size_t)BB*HH*32*128];
__device__ uint32_t g_qHkm_h[(size_t)BB*WW*32*128]; // [b*WW+w][dp][h]
__device__ uint32_t g_qHkm_l[(size_t)BB*WW*32*128];
__device__ uint32_t g_kHkm_h[(size_t)BB*WW*32*128];
__device__ uint32_t g_kHkm_l[(size_t)BB*WW*32*128];

// ---------------- helpers ----------------
__device__ __forceinline__ void split_pack(float v0, float v1, uint32_t& hi, uint32_t& lo){
    __nv_bfloat16 h0 = __float2bfloat16(v0);
    __nv_bfloat16 h1 = __float2bfloat16(v1);
    __nv_bfloat16 l0 = __float2bfloat16(v0 - __bfloat162float(h0));
    __nv_bfloat16 l1 = __float2bfloat16(v1 - __bfloat162float(h1));
    hi = ((uint32_t)__bfloat16_as_ushort(h1) << 16) | (uint32_t)__bfloat16_as_ushort(h0);
    lo = ((uint32_t)__bfloat16_as_ushort(l1) << 16) | (uint32_t)__bfloat16_as_ushort(l0);
}
__device__ __forceinline__ void mma_bf16(float* c, const uint32_t* a, const uint32_t* b){
    asm volatile("mma.sync.aligned.m16n8k16.row.col.f32.bf16.bf16.f32 "
        "{%0,%1,%2,%3}, {%4,%5,%6,%7}, {%8,%9}, {%0,%1,%2,%3};"
        : "+f"(c[0]), "+f"(c[1]), "+f"(c[2]), "+f"(c[3])
        : "r"(a[0]), "r"(a[1]), "r"(a[2]), "r"(a[3]), "r"(b[0]), "r"(b[1]));
}

// ---------------- pack W (tiny) ----------------
__global__ void __launch_bounds__(256) pack_W_kernel(const float* __restrict__ Wq,
                                                     const float* __restrict__ Wk,
                                                     const float* __restrict__ Wv)
{
    int u = blockIdx.x * 256 + threadIdx.x;
    if (u >= 256*160) return;
    int kp = u / 160;
    int m4 = u - kp*160;
    int m = m4*4;
    int c0 = 2*kp, c1 = 2*kp+1;
    float v0[4], v1[4];
    #pragma unroll
    for (int j = 0; j < 4; j++) {
        int mm = m + j;
        if (mm < 64)       { v0[j] = Wq[(size_t)c0*DQ + mm];       v1[j] = Wq[(size_t)c1*DQ + mm]; }
        else if (mm < 128) { v0[j] = Wk[(size_t)c0*DQ + mm-64];    v1[j] = Wk[(size_t)c1*DQ + mm-64]; }
        else               { v0[j] = Wv[(size_t)c0*CC + mm-128];   v1[j] = Wv[(size_t)c1*CC + mm-128]; }
    }
    uint4 hi, lo;
    split_pack(v0[0], v1[0], hi.x, lo.x);
    split_pack(v0[1], v1[1], hi.y, lo.y);
    split_pack(v0[2], v1[2], hi.z, lo.z);
    split_pack(v0[3], v1[3], hi.w, lo.w);
    *(uint4*)(g_Wp_h + (size_t)kp*640 + m) = hi;
    *(uint4*)(g_Wp_l + (size_t)kp*640 + m) = lo;
}

// ---------------- HMMA projection GEMM (double-buffered, split N-tile) --------
// N-tile = pixels {h=2j, 2j+1} x {w in [whalf*64, whalf*64+64)}; col n -> pixel
// offset pix(n) = ((n&64)<<1) + (n&63) relative to base (2j*128 + whalf*64).
extern __shared__ uint32_t dynS[];

__device__ __forceinline__ void proj_load_tile(int it, uint32_t* buf, int tid,
                                               int mTile, const float* __restrict__ xB)
{
    const int kp0 = it * 16;
    uint32_t* Ah = buf;
    uint32_t* Al = buf + TILE_U32;
    uint32_t* Bh = buf + 2*TILE_U32;
    uint32_t* Bl = buf + 3*TILE_U32;
    #pragma unroll
    for (int i = 0; i < 2; i++) {
        int f = tid + i*256;
        int kp = f >> 5, c4 = (f & 31) * 4;
        int pix = ((c4 & 64) << 1) + (c4 & 63);
        *(uint4*)&Ah[kp*136 + c4] = *(const uint4*)&g_Wp_h[(size_t)(kp0+kp)*640 + mTile + c4];
        *(uint4*)&Al[kp*136 + c4] = *(const uint4*)&g_Wp_l[(size_t)(kp0+kp)*640 + mTile + c4];
        const float* p0 = xB + (size_t)(2*(kp0+kp))*HWW + pix;
        float4 r0 = *(const float4*)p0;
        float4 r1 = *(const float4*)(p0 + HWW);
        uint4 bh4, bl4;
        split_pack(r0.x, r1.x, bh4.x, bl4.x);
        split_pack(r0.y, r1.y, bh4.y, bl4.y);
        split_pack(r0.z, r1.z, bh4.z, bl4.z);
        split_pack(r0.w, r1.w, bh4.w, bl4.w);
        *(uint4*)&Bh[kp*136 + c4] = bh4;
        *(uint4*)&Bl[kp*136 + c4] = bl4;
    }
}

__global__ void __launch_bounds__(256, 2) mma_proj_kernel(
    const float* __restrict__ x,
    const float* __restrict__ bq, const float* __restrict__ bk, const float* __restrict__ bvv)
{
    const int tid = threadIdx.x;
    const int wid = tid >> 5, lane = tid & 31;
    const int gid = lane >> 2, tig = lane & 3;
    const int wm0 = (wid >> 2) * 64;
    const int wn0 = (wid & 3) * 32;
    const int mTile = blockIdx.x * 128;
    const int jIdx = blockIdx.y >> 1;          // h-pair index
    const int whalf = blockIdx.y & 1;          // w half
    const int yBase = jIdx*256 + whalf*64;     // base pixel = 2j*128 + whalf*64
    const int b = blockIdx.z;

    float acc[4][4][4];
    #pragma unroll
    for (int i = 0; i < 4; i++)
        #pragma unroll
        for (int j = 0; j < 4; j++)
            #pragma unroll
            for (int r = 0; r < 4; r++) acc[i][j][r] = 0.f;

    const float* xB = x + (size_t)b*CC*HWW + yBase;

    proj_load_tile(0, dynS, tid, mTile, xB);
    __syncthreads();

    for (int it = 0; it < 16; ++it) {
        if (it < 15)
            proj_load_tile(it+1, dynS + ((it+1)&1)*BUF_U32, tid, mTile, xB);
        const uint32_t* Ah = dynS + (it&1)*BUF_U32;
        const uint32_t* Al = Ah + TILE_U32;
        const uint32_t* Bh = Ah + 2*TILE_U32;
        const uint32_t* Bl = Ah + 3*TILE_U32;
        #pragma unroll
        for (int ks = 0; ks < 2; ks++) {
            const int kb = ks * 8;
            uint32_t ah[4][4], al[4][4], bh[4][2], bl[4][2];
            #pragma unroll
            for (int mi = 0; mi < 4; mi++) {
                int m = wm0 + mi*16 + gid;
                ah[mi][0] = Ah[(kb+tig  )*136 + m];
                ah[mi][1] = Ah[(kb+tig  )*136 + m+8];
                ah[mi][2] = Ah[(kb+tig+4)*136 + m];
                ah[mi][3] = Ah[(kb+tig+4)*136 + m+8];
                al[mi][0] = Al[(kb+tig  )*136 + m];
                al[mi][1] = Al[(kb+tig  )*136 + m+8];
                al[mi][2] = Al[(kb+tig+4)*136 + m];
                al[mi][3] = Al[(kb+tig+4)*136 + m+8];
            }
            #pragma unroll
            for (int nj = 0; nj < 4; nj++) {
                int n = wn0 + nj*8 + gid;
                bh[nj][0] = Bh[(kb+tig  )*136 + n];
                bh[nj][1] = Bh[(kb+tig+4)*136 + n];
                bl[nj][0] = Bl[(kb+tig  )*136 + n];
                bl[nj][1] = Bl[(kb+tig+4)*136 + n];
            }
            #pragma unroll
            for (int mi = 0; mi < 4; mi++)
                #pragma unroll
                for (int nj = 0; nj < 4; nj++) {
                    mma_bf16(acc[mi][nj], ah[mi], bh[nj]);
                    mma_bf16(acc[mi][nj], ah[mi], bl[nj]);
                    mma_bf16(acc[mi][nj], al[mi], bh[nj]);
                }
        }
        __syncthreads();
    }

    if (mTile == 0) {
        // q/k rows -> fp32, pixel-remapped columns
        #pragma unroll
        for (int mi = 0; mi < 4; mi++) {
            #pragma unroll
            for (int half = 0; half < 2; half++) {
                int row = wm0 + mi*16 + gid + half*8;
                float bias; float* optr;
                if (row < 64) { bias = bq[row];    optr = g_q + ((size_t)b*DQ + row)     *HWW; }
                else          { bias = bk[row-64]; optr = g_k + ((size_t)b*DQ + (row-64))*HWW; }
                #pragma unroll
                for (int nj = 0; nj < 4; nj++) {
                    int n = wn0 + nj*8 + 2*tig;
                    int pix = ((n & 64) << 1) + (n & 63);
                    float2 f2;
                    f2.x = acc[mi][nj][half*2+0] + bias;
                    f2.y = acc[mi][nj][half*2+1] + bias;
                    *(float2*)(optr + yBase + pix) = f2;
                }
            }
        }
    } else {
        // v rows: stage fp32 tile to smem [n][c] (pitch 132), then pack both layouts
        float* smf = (float*)dynS;
        #pragma unroll
        for (int mi = 0; mi < 4; mi++) {
            #pragma unroll
            for (int half = 0; half < 2; half++) {
                int rowL = wm0 + mi*16 + gid + half*8;
                float bias = bvv[mTile - 128 + rowL];
                #pragma unroll
                for (int nj = 0; nj < 4; nj++) {
                    int col = wn0 + nj*8 + 2*tig;
                    smf[(col  )*132 + rowL] = acc[mi][nj][half*2+0] + bias;
                    smf[(col+1)*132 + rowL] = acc[mi][nj][half*2+1] + bias;
                }
            }
        }
        __syncthreads();
        const int cBase = mTile - 128;
        // vWkm: w-pairs.  n = hOff*64 + 2*wli (+1)
        #pragma unroll 4
        for (int itw = 0; itw < 32; itw++) {
            int u = tid + itw*256;
            int c = u & 127;
            int pr = u >> 7;                 // 0..63
            int hOff = pr >> 5, wli = pr & 31;
            int n = hOff*64 + 2*wli;
            uint32_t hh, ll;
            split_pack(smf[n*132 + c], smf[(n+1)*132 + c], hh, ll);
            size_t o = ((size_t)(b*HH + 2*jIdx + hOff)*64 + whalf*32 + wli)*512 + cBase + c;
            g_vWkm_h[o] = hh; g_vWkm_l[o] = ll;
        }
        // vHkm: h-pairs. values at n=wl (h=2j) and n=wl+64 (h=2j+1)
        #pragma unroll 4
        for (int ith = 0; ith < 32; ith++) {
            int u = tid + ith*256;
            int c = u & 127;
            int wl = u >> 7;                 // 0..63
            uint32_t hh, ll;
            split_pack(smf[wl*132 + c], smf[(wl+64)*132 + c], hh, ll);
            size_t o = ((size_t)(b*WW + whalf*64 + wl)*64 + jIdx)*512 + cBase + c;
            g_vHkm_h[o] = hh; g_vHkm_l[o] = ll;
        }
    }
}

// ---------------- packA/packB: q/k energy operands (validated R7) ----------------
__device__ __forceinline__ void packA_body(const float* __restrict__ src,
                                           uint32_t* __restrict__ dh,
                                           uint32_t* __restrict__ dl)
{
    __shared__ float t[32][33];
    int s = blockIdx.z;
    int b = s >> 7, h = s & 127;
    int w0 = blockIdx.x*32, d0 = blockIdx.y*32;
    int tx = threadIdx.x, ty = threadIdx.y;
    const float* S = src + (size_t)b*DQ*HWW + (size_t)h*WW;
    #pragma unroll
    for (int j = 0; j < 32; j += 8)
        t[ty+j][tx] = S[(size_t)(d0+ty+j)*HWW + w0 + tx];
    __syncthreads();
    #pragma unroll
    for (int j = 0; j < 16; j += 8) {
        int kp = ty + j;
        uint32_t hi, lo;
        split_pack(t[2*kp][tx], t[2*kp+1][tx], hi, lo);
        size_t o = ((size_t)s*32 + (d0>>1) + kp)*128 + w0 + tx;
        dh[o] = hi; dl[o] = lo;
    }
}
__global__ void packA_q_kernel(){ packA_body(g_q, g_qWkm_h, g_qWkm_l); }
__global__ void packA_k_kernel(){ packA_body(g_k, g_kWkm_h, g_kWkm_l); }

__device__ __forceinline__ void packB_body(const float* __restrict__ src,
                                           uint32_t* __restrict__ dh,
                                           uint32_t* __restrict__ dl)
{
    __shared__ float t[8][32][33];
    int z = blockIdx.z;
    int b = z >> 3, d0 = (z & 7) * 8;
    int w0 = blockIdx.x*32, h0 = blockIdx.y*32;
    int tid = threadIdx.x;
    int tx = tid & 31, ty = tid >> 5;
    #pragma unroll
    for (int dd = 0; dd < 8; dd++)
        #pragma unroll
        for (int j = 0; j < 32; j += 8)
            t[dd][ty+j][tx] = src[((size_t)b*DQ + d0+dd)*HWW + (size_t)(h0+ty+j)*WW + w0 + tx];
    __syncthreads();
    #pragma unroll
    for (int it = 0; it < 16; it++) {
        int idx = tid + it*256;
        int hl = idx & 31, wl = (idx >> 5) & 31, dpl = idx >> 10;
        uint32_t hi, lo;
        split_pack(t[2*dpl][hl][wl], t[2*dpl+1][hl][wl], hi, lo);
        size_t o = (((size_t)b*WW + w0 + wl)*32 + (d0>>1) + dpl)*128 + h0 + hl;
        dh[o] = hi; dl[o] = lo;
    }
}
__global__ void __launch_bounds__(256) packB_q_kernel(){ packB_body(g_q, g_qHkm_h, g_qHkm_l); }
__global__ void __launch_bounds__(256) packB_k_kernel(){ packB_body(g_k, g_kHkm_h, g_kHkm_l); }

// ---------------- energy: HMMA -> unnormalized packed att + stat partials (R9) ----
template<int MASK>
__device__ __forceinline__ void energy_mma_body(
    const uint32_t* __restrict__ Qh, const uint32_t* __restrict__ Ql,
    const uint32_t* __restrict__ Kh, const uint32_t* __restrict__ Kl,
    uint32_t* __restrict__ dh, uint32_t* __restrict__ dl,
    float2* __restrict__ statOut)
{
    __shared__ uint32_t sAh[16][136], sAl[16][136], sBh[16][136], sBl[16][136];
    __shared__ float red[128][17];
    __shared__ float rmax[128];

    const int tid = threadIdx.x;
    const int wid = tid >> 5, lane = tid & 31;
    const int gid = lane >> 2, tig = lane & 3;
    const int wm0 = (wid >> 2) * 64;
    const int wn0 = (wid & 3) * 32;
    const int cg  = (wid & 3) * 4 + tig;
    const int s = blockIdx.z;

    const uint32_t* Qh_s = Qh + (size_t)s*32*128;
    const uint32_t* Ql_s = Ql + (size_t)s*32*128;
    const uint32_t* Kh_s = Kh + (size_t)s*32*128;
    const uint32_t* Kl_s = Kl + (size_t)s*32*128;

    float acc[4][4][4];
    #pragma unroll
    for (int i = 0; i < 4; i++)
        #pragma unroll
        for (int j = 0; j < 4; j++)
            #pragma unroll
            for (int r = 0; r < 4; r++) acc[i][j][r] = 0.f;

    for (int ch = 0; ch < 2; ++ch) {
        const int kp0 = ch * 16;
        #pragma unroll
        for (int i = 0; i < 2; i++) {
            int f = tid + i*256;
            int kp = f >> 5, c4 = (f & 31) * 4;
            *(uint4*)&sAh[kp][c4] = *(const uint4*)(Qh_s + (size_t)(kp0+kp)*128 + c4);
            *(uint4*)&sAl[kp][c4] = *(const uint4*)(Ql_s + (size_t)(kp0+kp)*128 + c4);
            *(uint4*)&sBh[kp][c4] = *(const uint4*)(Kh_s + (size_t)(kp0+kp)*128 + c4);
            *(uint4*)&sBl[kp][c4] = *(const uint4*)(Kl_s + (size_t)(kp0+kp)*128 + c4);
        }
        __syncthreads();
        #pragma unroll
        for (int ks = 0; ks < 2; ks++) {
            const int kb = ks * 8;
            uint32_t ah[4][4], al[4][4], bh[4][2], bl[4][2];
            #pragma unroll
            for (int mi = 0; mi < 4; mi++) {
                int m = wm0 + mi*16 + gid;
                ah[mi][0] = sAh[kb+tig  ][m];
                ah[mi][1] = sAh[kb+tig  ][m+8];
                ah[mi][2] = sAh[kb+tig+4][m];
                ah[mi][3] = sAh[kb+tig+4][m+8];
                al[mi][0] = sAl[kb+tig  ][m];
                al[mi][1] = sAl[kb+tig  ][m+8];
                al[mi][2] = sAl[kb+tig+4][m];
                al[mi][3] = sAl[kb+tig+4][m+8];
            }
            #pragma unroll
            for (int nj = 0; nj < 4; nj++) {
                int n = wn0 + nj*8 + gid;
                bh[nj][0] = sBh[kb+tig  ][n];
                bh[nj][1] = sBh[kb+tig+4][n];
                bl[nj][0] = sBl[kb+tig  ][n];
                bl[nj][1] = sBl[kb+tig+4][n];
            }
            #pragma unroll
            for (int mi = 0; mi < 4; mi++)
                #pragma unroll
                for (int nj = 0; nj < 4; nj++) {
                    mma_bf16(acc[mi][nj], ah[mi], bh[nj]);
                    mma_bf16(acc[mi][nj], ah[mi], bl[nj]);
                    mma_bf16(acc[mi][nj], al[mi], bh[nj]);
                }
        }
        __syncthreads();
    }

    const float NINF = __int_as_float(0xff800000);
    if (MASK) {
        #pragma unroll
        for (int mi = 0; mi < 4; mi++)
            #pragma unroll
            for (int half = 0; half < 2; half++) {
                int row = wm0 + mi*16 + gid + half*8;
                #pragma unroll
                for (int nj = 0; nj < 4; nj++) {
                    int col = wn0 + nj*8 + 2*tig;
                    if (row == col)   acc[mi][nj][half*2+0] = NINF;
                    if (row == col+1) acc[mi][nj][half*2+1] = NINF;
                }
            }
    }

    #pragma unroll
    for (int mi = 0; mi < 4; mi++)
        #pragma unroll
        for (int half = 0; half < 2; half++) {
            int row = wm0 + mi*16 + gid + half*8;
            float m8 = NINF;
            #pragma unroll
            for (int nj = 0; nj < 4; nj++) {
                m8 = fmaxf(m8, acc[mi][nj][half*2+0]);
                m8 = fmaxf(m8, acc[mi][nj][half*2+1]);
            }
            red[row][cg] = m8;
        }
    __syncthreads();
    if (tid < 128) {
        float m = red[tid][0];
        #pragma unroll
        for (int j = 1; j < 16; j++) m = fmaxf(m, red[tid][j]);
        rmax[tid] = m;
    }
    __syncthreads();

    #pragma unroll
    for (int mi = 0; mi < 4; mi++)
        #pragma unroll
        for (int half = 0; half < 2; half++) {
            int row = wm0 + mi*16 + gid + half*8;
            float rm = rmax[row];
            float s8 = 0.f;
            #pragma unroll
            for (int nj = 0; nj < 4; nj++) {
                int col = wn0 + nj*8 + 2*tig;
                float e0 = __expf(acc[mi][nj][half*2+0] - rm);
                float e1 = __expf(acc[mi][nj][half*2+1] - rm);
                s8 += e0 + e1;
                uint32_t hi, lo;
                split_pack(e0, e1, hi, lo);
                size_t o = (size_t)s*8192 + (size_t)(col>>1)*128 + row;
                dh[o] = hi; dl[o] = lo;
            }
            red[row][cg] = s8;
        }
    __syncthreads();
    if (tid < 128) {
        float ssum = red[tid][0];
        #pragma unroll
        for (int j = 1; j < 16; j++) ssum += red[tid][j];
        statOut[(size_t)s*128 + tid] = make_float2(rmax[tid], ssum);
    }
}
__global__ void __launch_bounds__(256) energy_H_mma_kernel(){
    energy_mma_body<1>(g_qHkm_h, g_qHkm_l, g_kHkm_h, g_kHkm_l,
                       g_aHkm_h, g_aHkm_l, g_statH);
}
__global__ void __launch_bounds__(256) energy_W_mma_kernel(){
    energy_mma_body<0>(g_qWkm_h, g_qWkm_l, g_kWkm_h, g_kWkm_l,
                       g_aWkm_h, g_aWkm_l, g_statW);
}

// ---------------- merge stats -> per-orientation column factors (R9) --------------
__global__ void __launch_bounds__(256) combine_stat_kernel()
{
    int u = blockIdx.x*256 + threadIdx.x;   // b*HWW + h*WW + w
    int b = u >> 14;
    int hw = u & 16383;
    int h = hw >> 7, w = hw & 127;
    size_t iH = (size_t)(b*WW + w)*128 + h;
    size_t iW = (size_t)(b*HH + h)*128 + w;
    float2 sh = g_statH[iH];
    float2 sw = g_statW[iW];
    float m = fmaxf(sh.x, sw.x);
    float eh = __expf(sh.x - m), ew = __expf(sw.x - m);
    float invZ = 1.0f / (sh.y*eh + sw.y*ew);
    g_fH[iH] = eh * invZ;
    g_fW[iW] = ew * invZ;
}

// ---------------- HMMA aggregation (R13-validated, double-buffered) -----------
__device__ __forceinline__ void agg_load_tile(int ch, uint32_t* buf, int tid,
    const uint32_t* __restrict__ Vh_s, const uint32_t* __restrict__ Vl_s,
    const uint32_t* __restrict__ Ah_s, const uint32_t* __restrict__ Al_s)
{
    const int kp0 = ch * 16;
    uint32_t* Ah = buf;
    uint32_t* Al = buf + TILE_U32;
    uint32_t* Bh = buf + 2*TILE_U32;
    uint32_t* Bl = buf + 3*TILE_U32;
    #pragma unroll
    for (int i = 0; i < 2; i++) {
        int f = tid + i*256;
        int kp = f >> 5, c4 = (f & 31) * 4;
        *(uint4*)&Ah[kp*136 + c4] = *(const uint4*)(Vh_s + (size_t)(kp0+kp)*512 + c4);
        *(uint4*)&Al[kp*136 + c4] = *(const uint4*)(Vl_s + (size_t)(kp0+kp)*512 + c4);
        *(uint4*)&Bh[kp*136 + c4] = *(const uint4*)(Ah_s + (size_t)(kp0+kp)*128 + c4);
        *(uint4*)&Bl[kp*136 + c4] = *(const uint4*)(Al_s + (size_t)(kp0+kp)*128 + c4);
    }
}

__device__ __forceinline__ void agg_mma_body(
    const uint32_t* __restrict__ Vh, const uint32_t* __restrict__ Vl,
    const uint32_t* __restrict__ Ah_g, const uint32_t* __restrict__ Al_g,
    const float* __restrict__ fac,
    float* __restrict__ O, long oB, long oS, long oRow,
    const float* __restrict__ xAdd)
{
    __shared__ float sFac[128];

    const int tid = threadIdx.x;
    const int wid = tid >> 5, lane = tid & 31;
    const int gid = lane >> 2, tig = lane & 3;
    const int wm0 = (wid >> 2) * 64;
    const int wn0 = (wid & 3) * 32;
    const int mTile = blockIdx.x * 128;
    const int s = blockIdx.z;
    const int b = s >> 7, ss = s & 127;

    const uint32_t* Vh_s = Vh + (size_t)s*64*512 + mTile;
    const uint32_t* Vl_s = Vl + (size_t)s*64*512 + mTile;
    const uint32_t* Ah_s = Ah_g + (size_t)s*64*128;
    const uint32_t* Al_s = Al_g + (size_t)s*64*128;
    const size_t oBase = (size_t)b*oB + (size_t)ss*oS + (size_t)mTile*oRow;
    float* O_s = O + oBase;
    const float* X_s = xAdd ? (xAdd + oBase) : nullptr;

    if (tid < 128) sFac[tid] = fac[(size_t)s*128 + tid];

    float acc[4][4][4];
    #pragma unroll
    for (int i = 0; i < 4; i++)
        #pragma unroll
        for (int j = 0; j < 4; j++)
            #pragma unroll
            for (int r = 0; r < 4; r++) acc[i][j][r] = 0.f;

    agg_load_tile(0, dynS, tid, Vh_s, Vl_s, Ah_s, Al_s);
    __syncthreads();

    for (int ch = 0; ch < 4; ++ch) {
        if (ch < 3)
            agg_load_tile(ch+1, dynS + ((ch+1)&1)*BUF_U32, tid, Vh_s, Vl_s, Ah_s, Al_s);
        const uint32_t* Ah = dynS + (ch&1)*BUF_U32;
        const uint32_t* Al = Ah + TILE_U32;
        const uint32_t* Bh = Ah + 2*TILE_U32;
        const uint32_t* Bl = Ah + 3*TILE_U32;
        #pragma unroll
        for (int ks = 0; ks < 2; ks++) {
            const int kb = ks * 8;
            uint32_t ah[4][4], al[4][4], bh[4][2], bl[4][2];
            #pragma unroll
            for (int mi = 0; mi < 4; mi++) {
                int m = wm0 + mi*16 + gid;
                ah[mi][0] = Ah[(kb+tig  )*136 + m];
                ah[mi][1] = Ah[(kb+tig  )*136 + m+8];
                ah[mi][2] = Ah[(kb+tig+4)*136 + m];
                ah[mi][3] = Ah[(kb+tig+4)*136 + m+8];
                al[mi][0] = Al[(kb+tig  )*136 + m];
                al[mi][1] = Al[(kb+tig  )*136 + m+8];
                al[mi][2] = Al[(kb+tig+4)*136 + m];
                al[mi][3] = Al[(kb+tig+4)*136 + m+8];
            }
            #pragma unroll
            for (int nj = 0; nj < 4; nj++) {
                int n = wn0 + nj*8 + gid;
                bh[nj][0] = Bh[(kb+tig  )*136 + n];
                bh[nj][1] = Bh[(kb+tig+4)*136 + n];
                bl[nj][0] = Bl[(kb+tig  )*136 + n];
                bl[nj][1] = Bl[(kb+tig+4)*136 + n];
            }
            #pragma unroll
            for (int mi = 0; mi < 4; mi++)
                #pragma unroll
                for (int nj = 0; nj < 4; nj++) {
                    mma_bf16(acc[mi][nj], ah[mi], bh[nj]);
                    mma_bf16(acc[mi][nj], ah[mi], bl[nj]);
                    mma_bf16(acc[mi][nj], al[mi], bh[nj]);
                }
        }
        __syncthreads();
    }

    #pragma unroll
    for (int mi = 0; mi < 4; mi++) {
        #pragma unroll
        for (int half = 0; half < 2; half++) {
            int rowL = wm0 + mi*16 + gid + half*8;
            size_t roff = (size_t)rowL*oRow;
            #pragma unroll
            for (int nj = 0; nj < 4; nj++) {
                int col = wn0 + nj*8 + 2*tig;
                float2 f2;
                f2.x = acc[mi][nj][half*2+0] * sFac[col];
                f2.y = acc[mi][nj][half*2+1] * sFac[col+1];
                if (X_s) {
                    float2 xv = *(const float2*)(X_s + roff + col);
                    f2.x += xv.x; f2.y += xv.y;
                }
                *(float2*)(O_s + roff + col) = f2;
            }
        }
    }
}
__global__ void __launch_bounds__(256, 2) agg_H_mma_kernel(){
    agg_mma_body(g_vHkm_h, g_vHkm_l, g_aHkm_h, g_aHkm_l, g_fH, g_oH,
                 (long)WW*CC*HH, (long)CC*HH, (long)HH, nullptr);
}
__global__ void __launch_bounds__(256, 2) agg_W_mma_kernel(float* __restrict__ out,
                                                           const float* __restrict__ x){
    agg_mma_body(g_vWkm_h, g_vWkm_l, g_aWkm_h, g_aWkm_l, g_fW, out,
                 (long)CC*HWW, (long)WW, (long)HWW, x);
}

// ---------------- combine: out += GAMMA*out_H^T  (out already = out_W + x) ----------
__global__ void combine_kernel(float* __restrict__ out)
{
    __shared__ float t[32][33];
    int bc = blockIdx.z;
    int b = bc >> 9, c = bc & 511;
    int w0 = blockIdx.x*32, h0 = blockIdx.y*32;
    int tx = threadIdx.x, ty = threadIdx.y;
    #pragma unroll
    for (int k = 0; k < 32; k += 8) {
        int w = w0 + ty + k;
        int h = h0 + tx;
        t[ty+k][tx] = g_oH[(((size_t)b*WW + w)*CC + c)*HH + h];
    }
    __syncthreads();
    #pragma unroll
    for (int k = 0; k < 32; k += 8) {
        int h = h0 + ty + k;
        int w = w0 + tx;
        size_t idx = ((size_t)bc*HH + h)*WW + w;
        out[idx] = GAMMA_*t[tx][ty+k] + out[idx];
    }
}

// ---------------- launch ----------------
extern "C" void kernel_launch(void* const* d_in, const int* in_sizes, int n_in,
                              void* d_out, int out_size)
{
    const float* x  = (const float*)d_in[0];
    const float* Wq = (const float*)d_in[1];
    const float* bq = (const float*)d_in[2];
    const float* Wk = (const float*)d_in[3];
    const float* bk = (const float*)d_in[4];
    const float* Wv = (const float*)d_in[5];
    const float* bv = (const float*)d_in[6];
    float* out = (float*)d_out;

    cudaFuncSetAttribute(mma_proj_kernel,  cudaFuncAttributeMaxDynamicSharedMemorySize, DYN_SMEM_BYTES);
    cudaFuncSetAttribute(agg_H_mma_kernel, cudaFuncAttributeMaxDynamicSharedMemorySize, DYN_SMEM_BYTES);
    cudaFuncSetAttribute(agg_W_mma_kernel, cudaFuncAttributeMaxDynamicSharedMemorySize, DYN_SMEM_BYTES);

    dim3 tb(32, 8);

    pack_W_kernel<<<160, 256>>>(Wq, Wk, Wv);

    mma_proj_kernel<<<dim3(5, HWW/128, BB), 256, DYN_SMEM_BYTES>>>(x, bq, bk, bv);

    packA_q_kernel<<<dim3(4, 2, BB*HH), tb>>>();
    packA_k_kernel<<<dim3(4, 2, BB*HH), tb>>>();
    packB_q_kernel<<<dim3(4, 4, BB*8), 256>>>();
    packB_k_kernel<<<dim3(4, 4, BB*8), 256>>>();

    energy_H_mma_kernel<<<dim3(1, 1, BB*WW), 256>>>();
    energy_W_mma_kernel<<<dim3(1, 1, BB*HH), 256>>>();

    combine_stat_kernel<<<(BB*HWW)/256, 256>>>();

    agg_H_mma_kernel<<<dim3(4, 1, BB*WW), 256, DYN_SMEM_BYTES>>>();
    agg_W_mma_kernel<<<dim3(4, 1, BB*HH), 256, DYN_SMEM_BYTES>>>(out, x);

    combine_kernel<<<dim3(WW/32, HH/32, BB*CC), tb>>>(out);
}